// round 3
// baseline (speedup 1.0000x reference)
#include <cuda_runtime.h>
#include <cuda_bf16.h>
#include <stdint.h>

#define NCN 100000
#define NRN 100000
#define HD  64
#define EMAX 2000000
#define SCAN_BS 256

// ---------------- scratch (device globals: allocation-free) ----------------
__device__ float g_t_c[(size_t)NCN * HD];
__device__ float g_t_r[(size_t)NRN * HD];
__device__ float g_s_r[(size_t)NRN * HD];
__device__ float g_s_c[(size_t)NCN * HD];
__device__ float g_h_r[(size_t)NRN * HD];
__device__ float g_h_c[(size_t)NCN * HD];
__device__ int   g_dg_r[NRN];
__device__ int   g_dg_c[NCN];
__device__ int   g_off_r[NRN];
__device__ int   g_off_c[NCN];
__device__ int   g_cur_r[NRN];
__device__ int   g_cur_c[NCN];
__device__ int   g_csr_cr[EMAX];
__device__ int   g_csr_rc[EMAX];
__device__ int   g_bsum[1024];

// ---------------- kernels ----------------

__global__ void zero_i4(int4* __restrict__ p, int n4) {
    int i = blockIdx.x * blockDim.x + threadIdx.x;
    if (i < n4) p[i] = make_int4(0, 0, 0, 0);
}

__global__ void degree_k(const int* __restrict__ dst, int* __restrict__ deg, int nE) {
    int i = blockIdx.x * blockDim.x + threadIdx.x;
    if (i < nE) atomicAdd(deg + __ldg(dst + i), 1);
}

// --- 3-kernel exclusive scan over n<=100000 ints ---
__global__ void scan_block_k(const int* __restrict__ in, int* __restrict__ out,
                             int* __restrict__ bsum, int n) {
    __shared__ int sh[SCAN_BS];
    int i = blockIdx.x * SCAN_BS + threadIdx.x;
    int v = (i < n) ? in[i] : 0;
    sh[threadIdx.x] = v;
    __syncthreads();
    for (int off = 1; off < SCAN_BS; off <<= 1) {
        int t = (threadIdx.x >= off) ? sh[threadIdx.x - off] : 0;
        __syncthreads();
        sh[threadIdx.x] += t;
        __syncthreads();
    }
    if (i < n) out[i] = sh[threadIdx.x] - v;
    if (threadIdx.x == SCAN_BS - 1) bsum[blockIdx.x] = sh[threadIdx.x];
}

__global__ void scan_sums_k(int* __restrict__ bsum, int nb) {
    __shared__ int sh[1024];
    int v = (threadIdx.x < nb) ? bsum[threadIdx.x] : 0;
    sh[threadIdx.x] = v;
    __syncthreads();
    for (int off = 1; off < 1024; off <<= 1) {
        int t = (threadIdx.x >= off) ? sh[threadIdx.x - off] : 0;
        __syncthreads();
        sh[threadIdx.x] += t;
        __syncthreads();
    }
    if (threadIdx.x < nb) bsum[threadIdx.x] = sh[threadIdx.x] - v;
}

__global__ void scan_add_copy_k(int* __restrict__ out, int* __restrict__ cur,
                                const int* __restrict__ bsum, int n) {
    int i = blockIdx.x * SCAN_BS + threadIdx.x;
    if (i < n) {
        int v = out[i] + bsum[blockIdx.x];
        out[i] = v;
        cur[i] = v;
    }
}

__global__ void csr_fill_k(const int* __restrict__ src, const int* __restrict__ dst,
                           int* __restrict__ cur, int* __restrict__ csr, int nE) {
    int i = blockIdx.x * blockDim.x + threadIdx.x;
    if (i < nE) {
        int d = __ldg(dst + i);
        int p = atomicAdd(cur + d, 1);
        csr[p] = __ldg(src + i);
    }
}

// Y[n,64] = X[n,K] @ W[K,64].  W in smem; one thread per row.
// Inner product via packed fma.rn.f32x2 (2 fp32 MACs / instr, exact fp32).
__global__ void gemm_nk(const float* __restrict__ X, const float* __restrict__ W,
                        float* __restrict__ Y, int n, int K) {
    extern __shared__ float Ws[]; // K*64
    for (int i = threadIdx.x; i < K * HD; i += blockDim.x) Ws[i] = W[i];
    __syncthreads();
    int row = blockIdx.x * blockDim.x + threadIdx.x;
    if (row >= n) return;
    unsigned long long acc[32];
#pragma unroll
    for (int j = 0; j < 32; j++) acc[j] = 0ull;   // {0.f,0.f}
    const float* xr = X + (size_t)row * K;
    for (int k = 0; k < K; k += 4) {
        float4 xv = *reinterpret_cast<const float4*>(xr + k);
        float xs[4] = {xv.x, xv.y, xv.z, xv.w};
#pragma unroll
        for (int kk = 0; kk < 4; kk++) {
            unsigned long long xx;
            unsigned int xb = __float_as_uint(xs[kk]);
            asm("mov.b64 %0, {%1, %1};" : "=l"(xx) : "r"(xb));
            const ulonglong2* wrow = reinterpret_cast<const ulonglong2*>(Ws + (k + kk) * HD);
#pragma unroll
            for (int j = 0; j < 16; j++) {
                ulonglong2 w = wrow[j];
                asm("fma.rn.f32x2 %0, %1, %2, %0;" : "+l"(acc[2 * j])     : "l"(w.x), "l"(xx));
                asm("fma.rn.f32x2 %0, %1, %2, %0;" : "+l"(acc[2 * j + 1]) : "l"(w.y), "l"(xx));
            }
        }
    }
    float4* yr = reinterpret_cast<float4*>(Y + (size_t)row * HD);
#pragma unroll
    for (int j = 0; j < 16; j++) {
        unsigned int a0, a1, b0, b1;
        asm("mov.b64 {%0, %1}, %2;" : "=r"(a0), "=r"(a1) : "l"(acc[2 * j]));
        asm("mov.b64 {%0, %1}, %2;" : "=r"(b0), "=r"(b1) : "l"(acc[2 * j + 1]));
        yr[j] = make_float4(__uint_as_float(a0), __uint_as_float(a1),
                            __uint_as_float(b0), __uint_as_float(b1));
    }
}

// Fused gather-aggregate for BOTH relations in one launch.
// One warp per dst node; float2 per lane; 4 gathers in flight.
__global__ void aggregate2_k(
    const float* __restrict__ featA, const float* __restrict__ selfA,
    const float* __restrict__ biasA, const int* __restrict__ offsA,
    const int* __restrict__ degA, const int* __restrict__ csrA,
    float* __restrict__ outA, int nA,
    const float* __restrict__ featB, const float* __restrict__ selfB,
    const float* __restrict__ biasB, const int* __restrict__ offsB,
    const int* __restrict__ degB, const int* __restrict__ csrB,
    float* __restrict__ outB, int nB, int do_relu) {
    int w    = (blockIdx.x * blockDim.x + threadIdx.x) >> 5;
    int lane = threadIdx.x & 31;
    const float *feat, *self, *bias;
    const int *offs, *deg, *csr;
    float* out;
    if (w < nA) {
        feat = featA; self = selfA; bias = biasA; offs = offsA; deg = degA; csr = csrA; out = outA;
    } else {
        w -= nA;
        if (w >= nB) return;
        feat = featB; self = selfB; bias = biasB; offs = offsB; deg = degB; csr = csrB; out = outB;
    }
    int beg = __ldg(offs + w);
    int dg  = __ldg(deg + w);
    int end = beg + dg;
    float a0x = 0.f, a0y = 0.f, a1x = 0.f, a1y = 0.f;
    float a2x = 0.f, a2y = 0.f, a3x = 0.f, a3y = 0.f;
    int e = beg;
    for (; e + 3 < end; e += 4) {
        int s0 = __ldg(csr + e);
        int s1 = __ldg(csr + e + 1);
        int s2 = __ldg(csr + e + 2);
        int s3 = __ldg(csr + e + 3);
        float2 v0 = reinterpret_cast<const float2*>(feat + (size_t)s0 * HD)[lane];
        float2 v1 = reinterpret_cast<const float2*>(feat + (size_t)s1 * HD)[lane];
        float2 v2 = reinterpret_cast<const float2*>(feat + (size_t)s2 * HD)[lane];
        float2 v3 = reinterpret_cast<const float2*>(feat + (size_t)s3 * HD)[lane];
        a0x += v0.x; a0y += v0.y;
        a1x += v1.x; a1y += v1.y;
        a2x += v2.x; a2y += v2.y;
        a3x += v3.x; a3y += v3.y;
    }
    for (; e < end; e++) {
        int s0 = __ldg(csr + e);
        float2 v0 = reinterpret_cast<const float2*>(feat + (size_t)s0 * HD)[lane];
        a0x += v0.x; a0y += v0.y;
    }
    float ax = (a0x + a1x) + (a2x + a3x);
    float ay = (a0y + a1y) + (a2y + a3y);
    float inv = 1.f / (float)max(dg, 1);
    float2 sf = reinterpret_cast<const float2*>(self + (size_t)w * HD)[lane];
    float2 bb = reinterpret_cast<const float2*>(bias)[lane];
    float o0 = ax * inv + sf.x + bb.x;
    float o1 = ay * inv + sf.y + bb.y;
    if (do_relu) { o0 = fmaxf(o0, 0.f); o1 = fmaxf(o1, 0.f); }
    reinterpret_cast<float2*>(out + (size_t)w * HD)[lane] = make_float2(o0, o1);
}

// warp per supervision edge: out = relu(u_c[r]+u_r[c]+b1) . w2 + b2
__global__ void decode_k(const float* __restrict__ u_c, const float* __restrict__ u_r,
                         const int* __restrict__ rows, const int* __restrict__ cols,
                         const float* __restrict__ b1, const float* __restrict__ w2,
                         const float* __restrict__ b2, float* __restrict__ out, int L) {
    int gw   = (blockIdx.x * blockDim.x + threadIdx.x) >> 5;
    int lane = threadIdx.x & 31;
    if (gw >= L) return;
    int r = __ldg(rows + gw);
    int c = __ldg(cols + gw);
    float2 a  = reinterpret_cast<const float2*>(u_c + (size_t)r * HD)[lane];
    float2 b  = reinterpret_cast<const float2*>(u_r + (size_t)c * HD)[lane];
    float2 bb = reinterpret_cast<const float2*>(b1)[lane];
    float2 w  = reinterpret_cast<const float2*>(w2)[lane];
    float h0 = fmaxf(a.x + b.x + bb.x, 0.f);
    float h1 = fmaxf(a.y + b.y + bb.y, 0.f);
    float s = h0 * w.x + h1 * w.y;
#pragma unroll
    for (int off = 16; off; off >>= 1) s += __shfl_xor_sync(0xffffffffu, s, off);
    if (lane == 0) out[gw] = s + __ldg(b2);
}

// ---------------- launch ----------------

extern "C" void kernel_launch(void* const* d_in, const int* in_sizes, int n_in,
                              void* d_out, int out_size) {
    const float* x_c   = (const float*)d_in[0];
    const float* x_r   = (const float*)d_in[1];
    const float* W1crl = (const float*)d_in[2];
    const float* W1crr = (const float*)d_in[3];
    const float* b1cr  = (const float*)d_in[4];
    const float* W1rcl = (const float*)d_in[5];
    const float* W1rcr = (const float*)d_in[6];
    const float* b1rc  = (const float*)d_in[7];
    const float* W2crl = (const float*)d_in[8];
    const float* W2crr = (const float*)d_in[9];
    const float* b2cr  = (const float*)d_in[10];
    const float* W2rcl = (const float*)d_in[11];
    const float* W2rcr = (const float*)d_in[12];
    const float* b2rc  = (const float*)d_in[13];
    const float* Wd1   = (const float*)d_in[14];
    const float* bd1   = (const float*)d_in[15];
    const float* Wd2   = (const float*)d_in[16];
    const float* bd2   = (const float*)d_in[17];
    const int*   e_cr  = (const int*)d_in[18];
    const int*   e_rc  = (const int*)d_in[19];
    const int*   e_lab = (const int*)d_in[20];
    const int E_ = in_sizes[18] / 2;
    const int L_ = in_sizes[20] / 2;

    float *t_c, *t_r, *s_r, *s_c, *h_r, *h_c;
    int *dg_r, *dg_c, *off_r, *off_c, *cur_r, *cur_c, *csr_cr, *csr_rc, *bsum;
    cudaGetSymbolAddress((void**)&t_c, g_t_c);
    cudaGetSymbolAddress((void**)&t_r, g_t_r);
    cudaGetSymbolAddress((void**)&s_r, g_s_r);
    cudaGetSymbolAddress((void**)&s_c, g_s_c);
    cudaGetSymbolAddress((void**)&h_r, g_h_r);
    cudaGetSymbolAddress((void**)&h_c, g_h_c);
    cudaGetSymbolAddress((void**)&dg_r, g_dg_r);
    cudaGetSymbolAddress((void**)&dg_c, g_dg_c);
    cudaGetSymbolAddress((void**)&off_r, g_off_r);
    cudaGetSymbolAddress((void**)&off_c, g_off_c);
    cudaGetSymbolAddress((void**)&cur_r, g_cur_r);
    cudaGetSymbolAddress((void**)&cur_c, g_cur_c);
    cudaGetSymbolAddress((void**)&csr_cr, g_csr_cr);
    cudaGetSymbolAddress((void**)&csr_rc, g_csr_rc);
    cudaGetSymbolAddress((void**)&bsum, g_bsum);

    const int NT = 256;
    const int gD4  = (NCN / 4 + NT - 1) / NT;
    const int gRow = (NCN + NT - 1) / NT;
    const int gE   = (E_ + NT - 1) / NT;
    const int gN2w = ((NCN + NRN) * 32 + NT - 1) / NT;  // warps for both relations
    const int gLw  = (L_ * 32 + NT - 1) / NT;
    const int nScanB = (NCN + SCAN_BS - 1) / SCAN_BS;

    const int* cr_s = e_cr;   const int* cr_d = e_cr + E_;
    const int* rc_s = e_rc;   const int* rc_d = e_rc + E_;
    const int* lb_r = e_lab;  const int* lb_c = e_lab + L_;

    // ---- degrees ----
    zero_i4<<<gD4, NT>>>((int4*)dg_r, NRN / 4);
    zero_i4<<<gD4, NT>>>((int4*)dg_c, NCN / 4);
    degree_k<<<gE, NT>>>(cr_d, dg_r, E_);
    degree_k<<<gE, NT>>>(rc_d, dg_c, E_);

    // ---- CSR build ----
    scan_block_k<<<nScanB, SCAN_BS>>>(dg_r, off_r, bsum, NRN);
    scan_sums_k<<<1, 1024>>>(bsum, nScanB);
    scan_add_copy_k<<<nScanB, SCAN_BS>>>(off_r, cur_r, bsum, NRN);
    csr_fill_k<<<gE, NT>>>(cr_s, cr_d, cur_r, csr_cr, E_);
    scan_block_k<<<nScanB, SCAN_BS>>>(dg_c, off_c, bsum, NCN);
    scan_sums_k<<<1, 1024>>>(bsum, nScanB);
    scan_add_copy_k<<<nScanB, SCAN_BS>>>(off_c, cur_c, bsum, NCN);
    csr_fill_k<<<gE, NT>>>(rc_s, rc_d, cur_c, csr_rc, E_);

    // ---- layer 1 transforms ----
    gemm_nk<<<gRow, NT, 128 * HD * sizeof(float)>>>(x_c, W1crl, t_c, NCN, 128);
    gemm_nk<<<gRow, NT,  64 * HD * sizeof(float)>>>(x_r, W1crr, s_r, NRN, 64);
    gemm_nk<<<gRow, NT,  64 * HD * sizeof(float)>>>(x_r, W1rcl, t_r, NRN, 64);
    gemm_nk<<<gRow, NT, 128 * HD * sizeof(float)>>>(x_c, W1rcr, s_c, NCN, 128);

    // ---- layer 1 aggregate (both relations fused, relu) ----
    aggregate2_k<<<gN2w, NT>>>(t_c, s_r, b1cr, off_r, dg_r, csr_cr, h_r, NRN,
                               t_r, s_c, b1rc, off_c, dg_c, csr_rc, h_c, NCN, 1);

    // ---- layer 2 transforms ----
    gemm_nk<<<gRow, NT, 64 * HD * sizeof(float)>>>(h_c, W2crl, t_c, NCN, 64);
    gemm_nk<<<gRow, NT, 64 * HD * sizeof(float)>>>(h_r, W2crr, s_r, NRN, 64);
    gemm_nk<<<gRow, NT, 64 * HD * sizeof(float)>>>(h_r, W2rcl, t_r, NRN, 64);
    gemm_nk<<<gRow, NT, 64 * HD * sizeof(float)>>>(h_c, W2rcr, s_c, NCN, 64);

    // ---- layer 2 aggregate (both relations fused, no relu) ----
    aggregate2_k<<<gN2w, NT>>>(t_c, s_r, b2cr, off_r, dg_r, csr_cr, h_r, NRN,
                               t_r, s_c, b2rc, off_c, dg_c, csr_rc, h_c, NCN, 0);

    // ---- decoder precompute ----
    gemm_nk<<<gRow, NT, 64 * HD * sizeof(float)>>>(h_c, Wd1,           t_c, NCN, 64);
    gemm_nk<<<gRow, NT, 64 * HD * sizeof(float)>>>(h_r, Wd1 + 64 * HD, t_r, NRN, 64);

    // ---- decode ----
    decode_k<<<gLw, NT>>>(t_c, t_r, lb_r, lb_c, bd1, Wd2, bd2, (float*)d_out, L_);
}

// round 4
// speedup vs baseline: 1.0819x; 1.0819x over previous
#include <cuda_runtime.h>
#include <cuda_bf16.h>
#include <stdint.h>

#define NCN 100000
#define NRN 100000
#define HD  64
#define EMAX 2000000
#define SCAN_BS 256

// ---------------- scratch (device globals: allocation-free) ----------------
__device__ float g_t_c[(size_t)NCN * HD];
__device__ float g_t_r[(size_t)NRN * HD];
__device__ float g_s_r[(size_t)NRN * HD];
__device__ float g_s_c[(size_t)NCN * HD];
__device__ float g_h_r[(size_t)NRN * HD];
__device__ float g_h_c[(size_t)NCN * HD];
__device__ int   g_dg_r[NRN];
__device__ int   g_dg_c[NCN];
__device__ int   g_off_r[NRN];
__device__ int   g_off_c[NCN];
__device__ int   g_cur_r[NRN];
__device__ int   g_cur_c[NCN];
__device__ int   g_csr_cr[EMAX];
__device__ int   g_csr_rc[EMAX];
__device__ int   g_bsum[1024];
// folded decoder weights/biases
__device__ float g_wc_crl[HD * HD];  // W2crl @ Wd_bot   (msg c->r, feeds u_r)
__device__ float g_wc_crr[HD * HD];  // W2crr @ Wd_bot   (self r,  feeds u_r)
__device__ float g_wc_rcl[HD * HD];  // W2rcl @ Wd_top   (msg r->c, feeds u_c)
__device__ float g_wc_rcr[HD * HD];  // W2rcr @ Wd_top   (self c,  feeds u_c)
__device__ float g_bc_r[HD];         // b2cr @ Wd_bot
__device__ float g_bc_c[HD];         // b2rc @ Wd_top

// ---------------- kernels ----------------

__global__ void zero_i4(int4* __restrict__ p, int n4) {
    int i = blockIdx.x * blockDim.x + threadIdx.x;
    if (i < n4) p[i] = make_int4(0, 0, 0, 0);
}

__global__ void degree_k(const int* __restrict__ dst, int* __restrict__ deg, int nE) {
    int i = blockIdx.x * blockDim.x + threadIdx.x;
    if (i < nE) atomicAdd(deg + __ldg(dst + i), 1);
}

// --- 3-kernel exclusive scan over n<=100000 ints ---
__global__ void scan_block_k(const int* __restrict__ in, int* __restrict__ out,
                             int* __restrict__ bsum, int n) {
    __shared__ int sh[SCAN_BS];
    int i = blockIdx.x * SCAN_BS + threadIdx.x;
    int v = (i < n) ? in[i] : 0;
    sh[threadIdx.x] = v;
    __syncthreads();
    for (int off = 1; off < SCAN_BS; off <<= 1) {
        int t = (threadIdx.x >= off) ? sh[threadIdx.x - off] : 0;
        __syncthreads();
        sh[threadIdx.x] += t;
        __syncthreads();
    }
    if (i < n) out[i] = sh[threadIdx.x] - v;
    if (threadIdx.x == SCAN_BS - 1) bsum[blockIdx.x] = sh[threadIdx.x];
}

__global__ void scan_sums_k(int* __restrict__ bsum, int nb) {
    __shared__ int sh[1024];
    int v = (threadIdx.x < nb) ? bsum[threadIdx.x] : 0;
    sh[threadIdx.x] = v;
    __syncthreads();
    for (int off = 1; off < 1024; off <<= 1) {
        int t = (threadIdx.x >= off) ? sh[threadIdx.x - off] : 0;
        __syncthreads();
        sh[threadIdx.x] += t;
        __syncthreads();
    }
    if (threadIdx.x < nb) bsum[threadIdx.x] = sh[threadIdx.x] - v;
}

__global__ void scan_add_copy_k(int* __restrict__ out, int* __restrict__ cur,
                                const int* __restrict__ bsum, int n) {
    int i = blockIdx.x * SCAN_BS + threadIdx.x;
    if (i < n) {
        int v = out[i] + bsum[blockIdx.x];
        out[i] = v;
        cur[i] = v;
    }
}

__global__ void csr_fill_k(const int* __restrict__ src, const int* __restrict__ dst,
                           int* __restrict__ cur, int* __restrict__ csr, int nE) {
    int i = blockIdx.x * blockDim.x + threadIdx.x;
    if (i < nE) {
        int d = __ldg(dst + i);
        int p = atomicAdd(cur + d, 1);
        csr[p] = __ldg(src + i);
    }
}

// C[64,64] = A[64,64] @ B[64,64]; block = one output row, thread = one column.
__global__ void matmul64_k(const float* __restrict__ A, const float* __restrict__ B,
                           float* __restrict__ C) {
    __shared__ float Ar[HD];
    int r = blockIdx.x, j = threadIdx.x;
    if (j < HD) Ar[j] = A[r * HD + j];
    __syncthreads();
    float s = 0.f;
#pragma unroll 16
    for (int k = 0; k < HD; k++) s += Ar[k] * B[k * HD + j];
    C[r * HD + j] = s;
}

// out[64] = b[64] @ W[64,64]
__global__ void vecmat64_k(const float* __restrict__ b, const float* __restrict__ W,
                           float* __restrict__ out) {
    int j = threadIdx.x;
    float s = 0.f;
#pragma unroll 16
    for (int k = 0; k < HD; k++) s += b[k] * W[k * HD + j];
    out[j] = s;
}

// Y[n,64] = X[n,K] @ W[K,64].  W cached in shared; one thread per row.
__global__ void gemm_nk(const float* __restrict__ X, const float* __restrict__ W,
                        float* __restrict__ Y, int n, int K) {
    extern __shared__ float Ws[]; // K*64
    for (int i = threadIdx.x; i < K * HD; i += blockDim.x) Ws[i] = W[i];
    __syncthreads();
    int row = blockIdx.x * blockDim.x + threadIdx.x;
    if (row >= n) return;
    float acc[HD];
#pragma unroll
    for (int j = 0; j < HD; j++) acc[j] = 0.f;
    const float* xr = X + (size_t)row * K;
    for (int k = 0; k < K; k += 4) {
        float4 xv = *reinterpret_cast<const float4*>(xr + k);
        float xs[4] = {xv.x, xv.y, xv.z, xv.w};
#pragma unroll
        for (int kk = 0; kk < 4; kk++) {
            const float4* wrow = reinterpret_cast<const float4*>(Ws + (k + kk) * HD);
            float x = xs[kk];
#pragma unroll
            for (int j4 = 0; j4 < HD / 4; j4++) {
                float4 w = wrow[j4];
                acc[j4 * 4 + 0] += x * w.x;
                acc[j4 * 4 + 1] += x * w.y;
                acc[j4 * 4 + 2] += x * w.z;
                acc[j4 * 4 + 3] += x * w.w;
            }
        }
    }
    float4* yr = reinterpret_cast<float4*>(Y + (size_t)row * HD);
#pragma unroll
    for (int j4 = 0; j4 < HD / 4; j4++)
        yr[j4] = make_float4(acc[j4 * 4], acc[j4 * 4 + 1], acc[j4 * 4 + 2], acc[j4 * 4 + 3]);
}

// Fused gather-aggregate for BOTH relations in one launch.
// One warp per dst node; float2 per lane; 4 gathers in flight.
__global__ void aggregate2_k(
    const float* __restrict__ featA, const float* __restrict__ selfA,
    const float* __restrict__ biasA, const int* __restrict__ offsA,
    const int* __restrict__ degA, const int* __restrict__ csrA,
    float* __restrict__ outA, int nA,
    const float* __restrict__ featB, const float* __restrict__ selfB,
    const float* __restrict__ biasB, const int* __restrict__ offsB,
    const int* __restrict__ degB, const int* __restrict__ csrB,
    float* __restrict__ outB, int nB, int do_relu) {
    int w    = (blockIdx.x * blockDim.x + threadIdx.x) >> 5;
    int lane = threadIdx.x & 31;
    const float *feat, *self, *bias;
    const int *offs, *deg, *csr;
    float* out;
    if (w < nA) {
        feat = featA; self = selfA; bias = biasA; offs = offsA; deg = degA; csr = csrA; out = outA;
    } else {
        w -= nA;
        if (w >= nB) return;
        feat = featB; self = selfB; bias = biasB; offs = offsB; deg = degB; csr = csrB; out = outB;
    }
    int beg = __ldg(offs + w);
    int dg  = __ldg(deg + w);
    int end = beg + dg;
    float a0x = 0.f, a0y = 0.f, a1x = 0.f, a1y = 0.f;
    float a2x = 0.f, a2y = 0.f, a3x = 0.f, a3y = 0.f;
    int e = beg;
    for (; e + 3 < end; e += 4) {
        int s0 = __ldg(csr + e);
        int s1 = __ldg(csr + e + 1);
        int s2 = __ldg(csr + e + 2);
        int s3 = __ldg(csr + e + 3);
        float2 v0 = reinterpret_cast<const float2*>(feat + (size_t)s0 * HD)[lane];
        float2 v1 = reinterpret_cast<const float2*>(feat + (size_t)s1 * HD)[lane];
        float2 v2 = reinterpret_cast<const float2*>(feat + (size_t)s2 * HD)[lane];
        float2 v3 = reinterpret_cast<const float2*>(feat + (size_t)s3 * HD)[lane];
        a0x += v0.x; a0y += v0.y;
        a1x += v1.x; a1y += v1.y;
        a2x += v2.x; a2y += v2.y;
        a3x += v3.x; a3y += v3.y;
    }
    for (; e < end; e++) {
        int s0 = __ldg(csr + e);
        float2 v0 = reinterpret_cast<const float2*>(feat + (size_t)s0 * HD)[lane];
        a0x += v0.x; a0y += v0.y;
    }
    float ax = (a0x + a1x) + (a2x + a3x);
    float ay = (a0y + a1y) + (a2y + a3y);
    float inv = 1.f / (float)max(dg, 1);
    float2 sf = reinterpret_cast<const float2*>(self + (size_t)w * HD)[lane];
    float2 bb = reinterpret_cast<const float2*>(bias)[lane];
    float o0 = ax * inv + sf.x + bb.x;
    float o1 = ay * inv + sf.y + bb.y;
    if (do_relu) { o0 = fmaxf(o0, 0.f); o1 = fmaxf(o1, 0.f); }
    reinterpret_cast<float2*>(out + (size_t)w * HD)[lane] = make_float2(o0, o1);
}

// warp per supervision edge: out = relu(u_c[r]+u_r[c]+b1) . w2 + b2
__global__ void decode_k(const float* __restrict__ u_c, const float* __restrict__ u_r,
                         const int* __restrict__ rows, const int* __restrict__ cols,
                         const float* __restrict__ b1, const float* __restrict__ w2,
                         const float* __restrict__ b2, float* __restrict__ out, int L) {
    int gw   = (blockIdx.x * blockDim.x + threadIdx.x) >> 5;
    int lane = threadIdx.x & 31;
    if (gw >= L) return;
    int r = __ldg(rows + gw);
    int c = __ldg(cols + gw);
    float2 a  = reinterpret_cast<const float2*>(u_c + (size_t)r * HD)[lane];
    float2 b  = reinterpret_cast<const float2*>(u_r + (size_t)c * HD)[lane];
    float2 bb = reinterpret_cast<const float2*>(b1)[lane];
    float2 w  = reinterpret_cast<const float2*>(w2)[lane];
    float h0 = fmaxf(a.x + b.x + bb.x, 0.f);
    float h1 = fmaxf(a.y + b.y + bb.y, 0.f);
    float s = h0 * w.x + h1 * w.y;
#pragma unroll
    for (int off = 16; off; off >>= 1) s += __shfl_xor_sync(0xffffffffu, s, off);
    if (lane == 0) out[gw] = s + __ldg(b2);
}

// ---------------- launch ----------------

extern "C" void kernel_launch(void* const* d_in, const int* in_sizes, int n_in,
                              void* d_out, int out_size) {
    const float* x_c   = (const float*)d_in[0];
    const float* x_r   = (const float*)d_in[1];
    const float* W1crl = (const float*)d_in[2];
    const float* W1crr = (const float*)d_in[3];
    const float* b1cr  = (const float*)d_in[4];
    const float* W1rcl = (const float*)d_in[5];
    const float* W1rcr = (const float*)d_in[6];
    const float* b1rc  = (const float*)d_in[7];
    const float* W2crl = (const float*)d_in[8];
    const float* W2crr = (const float*)d_in[9];
    const float* b2cr  = (const float*)d_in[10];
    const float* W2rcl = (const float*)d_in[11];
    const float* W2rcr = (const float*)d_in[12];
    const float* b2rc  = (const float*)d_in[13];
    const float* Wd1   = (const float*)d_in[14];  // [128,64]: top 64 rows for z_c, bottom for z_r
    const float* bd1   = (const float*)d_in[15];
    const float* Wd2   = (const float*)d_in[16];
    const float* bd2   = (const float*)d_in[17];
    const int*   e_cr  = (const int*)d_in[18];
    const int*   e_rc  = (const int*)d_in[19];
    const int*   e_lab = (const int*)d_in[20];
    const int E_ = in_sizes[18] / 2;
    const int L_ = in_sizes[20] / 2;

    float *t_c, *t_r, *s_r, *s_c, *h_r, *h_c;
    float *wc_crl, *wc_crr, *wc_rcl, *wc_rcr, *bc_r, *bc_c;
    int *dg_r, *dg_c, *off_r, *off_c, *cur_r, *cur_c, *csr_cr, *csr_rc, *bsum;
    cudaGetSymbolAddress((void**)&t_c, g_t_c);
    cudaGetSymbolAddress((void**)&t_r, g_t_r);
    cudaGetSymbolAddress((void**)&s_r, g_s_r);
    cudaGetSymbolAddress((void**)&s_c, g_s_c);
    cudaGetSymbolAddress((void**)&h_r, g_h_r);
    cudaGetSymbolAddress((void**)&h_c, g_h_c);
    cudaGetSymbolAddress((void**)&dg_r, g_dg_r);
    cudaGetSymbolAddress((void**)&dg_c, g_dg_c);
    cudaGetSymbolAddress((void**)&off_r, g_off_r);
    cudaGetSymbolAddress((void**)&off_c, g_off_c);
    cudaGetSymbolAddress((void**)&cur_r, g_cur_r);
    cudaGetSymbolAddress((void**)&cur_c, g_cur_c);
    cudaGetSymbolAddress((void**)&csr_cr, g_csr_cr);
    cudaGetSymbolAddress((void**)&csr_rc, g_csr_rc);
    cudaGetSymbolAddress((void**)&bsum, g_bsum);
    cudaGetSymbolAddress((void**)&wc_crl, g_wc_crl);
    cudaGetSymbolAddress((void**)&wc_crr, g_wc_crr);
    cudaGetSymbolAddress((void**)&wc_rcl, g_wc_rcl);
    cudaGetSymbolAddress((void**)&wc_rcr, g_wc_rcr);
    cudaGetSymbolAddress((void**)&bc_r, g_bc_r);
    cudaGetSymbolAddress((void**)&bc_c, g_bc_c);

    const int NT = 256;
    const int gD4  = (NCN / 4 + NT - 1) / NT;
    const int gRow = (NCN + NT - 1) / NT;
    const int gE   = (E_ + NT - 1) / NT;
    const int gN2w = ((NCN + NRN) * 32 + NT - 1) / NT;
    const int gLw  = (L_ * 32 + NT - 1) / NT;
    const int nScanB = (NCN + SCAN_BS - 1) / SCAN_BS;

    const int* cr_s = e_cr;   const int* cr_d = e_cr + E_;
    const int* rc_s = e_rc;   const int* rc_d = e_rc + E_;
    const int* lb_r = e_lab;  const int* lb_c = e_lab + L_;

    const float* Wd_top = Wd1;            // rows 0..63  (z_c half)
    const float* Wd_bot = Wd1 + HD * HD;  // rows 64..127 (z_r half)

    // ---- fold decoder into layer-2 weights (tiny) ----
    matmul64_k<<<HD, HD>>>(W2crl, Wd_bot, wc_crl);
    matmul64_k<<<HD, HD>>>(W2crr, Wd_bot, wc_crr);
    matmul64_k<<<HD, HD>>>(W2rcl, Wd_top, wc_rcl);
    matmul64_k<<<HD, HD>>>(W2rcr, Wd_top, wc_rcr);
    vecmat64_k<<<1, HD>>>(b2cr, Wd_bot, bc_r);
    vecmat64_k<<<1, HD>>>(b2rc, Wd_top, bc_c);

    // ---- degrees ----
    zero_i4<<<gD4, NT>>>((int4*)dg_r, NRN / 4);
    zero_i4<<<gD4, NT>>>((int4*)dg_c, NCN / 4);
    degree_k<<<gE, NT>>>(cr_d, dg_r, E_);
    degree_k<<<gE, NT>>>(rc_d, dg_c, E_);

    // ---- CSR build ----
    scan_block_k<<<nScanB, SCAN_BS>>>(dg_r, off_r, bsum, NRN);
    scan_sums_k<<<1, 1024>>>(bsum, nScanB);
    scan_add_copy_k<<<nScanB, SCAN_BS>>>(off_r, cur_r, bsum, NRN);
    csr_fill_k<<<gE, NT>>>(cr_s, cr_d, cur_r, csr_cr, E_);
    scan_block_k<<<nScanB, SCAN_BS>>>(dg_c, off_c, bsum, NCN);
    scan_sums_k<<<1, 1024>>>(bsum, nScanB);
    scan_add_copy_k<<<nScanB, SCAN_BS>>>(off_c, cur_c, bsum, NCN);
    csr_fill_k<<<gE, NT>>>(rc_s, rc_d, cur_c, csr_rc, E_);

    // ---- layer 1 transforms ----
    gemm_nk<<<gRow, NT, 128 * HD * sizeof(float)>>>(x_c, W1crl, t_c, NCN, 128);
    gemm_nk<<<gRow, NT,  64 * HD * sizeof(float)>>>(x_r, W1crr, s_r, NRN, 64);
    gemm_nk<<<gRow, NT,  64 * HD * sizeof(float)>>>(x_r, W1rcl, t_r, NRN, 64);
    gemm_nk<<<gRow, NT, 128 * HD * sizeof(float)>>>(x_c, W1rcr, s_c, NCN, 128);

    // ---- layer 1 aggregate (both relations fused, relu) ----
    aggregate2_k<<<gN2w, NT>>>(t_c, s_r, b1cr, off_r, dg_r, csr_cr, h_r, NRN,
                               t_r, s_c, b1rc, off_c, dg_c, csr_rc, h_c, NCN, 1);

    // ---- layer 2 transforms, pre-multiplied into decoder space ----
    gemm_nk<<<gRow, NT, 64 * HD * sizeof(float)>>>(h_c, wc_crl, t_c, NCN, 64); // msg c->r
    gemm_nk<<<gRow, NT, 64 * HD * sizeof(float)>>>(h_r, wc_crr, s_r, NRN, 64); // self r
    gemm_nk<<<gRow, NT, 64 * HD * sizeof(float)>>>(h_r, wc_rcl, t_r, NRN, 64); // msg r->c
    gemm_nk<<<gRow, NT, 64 * HD * sizeof(float)>>>(h_c, wc_rcr, s_c, NCN, 64); // self c

    // ---- layer 2 aggregate -> directly u_r (in h_r) and u_c (in h_c) ----
    aggregate2_k<<<gN2w, NT>>>(t_c, s_r, bc_r, off_r, dg_r, csr_cr, h_r, NRN,
                               t_r, s_c, bc_c, off_c, dg_c, csr_rc, h_c, NCN, 0);

    // ---- decode (u_c = h_c, u_r = h_r) ----
    decode_k<<<gLw, NT>>>(h_c, h_r, lb_r, lb_c, bd1, Wd2, bd2, (float*)d_out, L_);
}

// round 5
// speedup vs baseline: 1.3111x; 1.2119x over previous
#include <cuda_runtime.h>
#include <cuda_bf16.h>
#include <stdint.h>

#define NCN 100000
#define NRN 100000
#define HD  64
#define EMAX 2000000
#define SCAN_BS 256

// ---------------- scratch (device globals: allocation-free) ----------------
__device__ float g_t_c[(size_t)NCN * HD];
__device__ float g_t_r[(size_t)NRN * HD];
__device__ float g_s_r[(size_t)NRN * HD];
__device__ float g_s_c[(size_t)NCN * HD];
__device__ float g_h_r[(size_t)NRN * HD];
__device__ float g_h_c[(size_t)NCN * HD];
__device__ int   g_dg_r[NRN];
__device__ int   g_dg_c[NCN];
__device__ int   g_off_r[NRN];
__device__ int   g_off_c[NCN];
__device__ int   g_cur_r[NRN];
__device__ int   g_cur_c[NCN];
__device__ int   g_csr_cr[EMAX];
__device__ int   g_csr_rc[EMAX];
__device__ int   g_bsum[1024];
// folded decoder weights/biases
__device__ float g_wc_crl[HD * HD];  // W2crl @ Wd_bot   (msg c->r, feeds u_r)
__device__ float g_wc_crr[HD * HD];  // W2crr @ Wd_bot   (self r,  feeds u_r)
__device__ float g_wc_rcl[HD * HD];  // W2rcl @ Wd_top   (msg r->c, feeds u_c)
__device__ float g_wc_rcr[HD * HD];  // W2rcr @ Wd_top   (self c,  feeds u_c)
__device__ float g_bc_r[HD];         // b2cr @ Wd_bot
__device__ float g_bc_c[HD];         // b2rc @ Wd_top

// ---------------- kernels ----------------

__global__ void zero_i4(int4* __restrict__ p, int n4) {
    int i = blockIdx.x * blockDim.x + threadIdx.x;
    if (i < n4) p[i] = make_int4(0, 0, 0, 0);
}

__global__ void degree_k(const int* __restrict__ dst, int* __restrict__ deg, int nE) {
    int i = blockIdx.x * blockDim.x + threadIdx.x;
    if (i < nE) atomicAdd(deg + __ldg(dst + i), 1);
}

// --- 3-kernel exclusive scan over n<=100000 ints ---
__global__ void scan_block_k(const int* __restrict__ in, int* __restrict__ out,
                             int* __restrict__ bsum, int n) {
    __shared__ int sh[SCAN_BS];
    int i = blockIdx.x * SCAN_BS + threadIdx.x;
    int v = (i < n) ? in[i] : 0;
    sh[threadIdx.x] = v;
    __syncthreads();
    for (int off = 1; off < SCAN_BS; off <<= 1) {
        int t = (threadIdx.x >= off) ? sh[threadIdx.x - off] : 0;
        __syncthreads();
        sh[threadIdx.x] += t;
        __syncthreads();
    }
    if (i < n) out[i] = sh[threadIdx.x] - v;
    if (threadIdx.x == SCAN_BS - 1) bsum[blockIdx.x] = sh[threadIdx.x];
}

__global__ void scan_sums_k(int* __restrict__ bsum, int nb) {
    __shared__ int sh[1024];
    int v = (threadIdx.x < nb) ? bsum[threadIdx.x] : 0;
    sh[threadIdx.x] = v;
    __syncthreads();
    for (int off = 1; off < 1024; off <<= 1) {
        int t = (threadIdx.x >= off) ? sh[threadIdx.x - off] : 0;
        __syncthreads();
        sh[threadIdx.x] += t;
        __syncthreads();
    }
    if (threadIdx.x < nb) bsum[threadIdx.x] = sh[threadIdx.x] - v;
}

__global__ void scan_add_copy_k(int* __restrict__ out, int* __restrict__ cur,
                                const int* __restrict__ bsum, int n) {
    int i = blockIdx.x * SCAN_BS + threadIdx.x;
    if (i < n) {
        int v = out[i] + bsum[blockIdx.x];
        out[i] = v;
        cur[i] = v;
    }
}

__global__ void csr_fill_k(const int* __restrict__ src, const int* __restrict__ dst,
                           int* __restrict__ cur, int* __restrict__ csr, int nE) {
    int i = blockIdx.x * blockDim.x + threadIdx.x;
    if (i < nE) {
        int d = __ldg(dst + i);
        int p = atomicAdd(cur + d, 1);
        csr[p] = __ldg(src + i);
    }
}

// One launch for the whole decoder fold:
//   blocks 0..63    : wc_crl row  = W2crl[row] @ Wd_bot
//   blocks 64..127  : wc_crr row  = W2crr[row] @ Wd_bot
//   blocks 128..191 : wc_rcl row  = W2rcl[row] @ Wd_top
//   blocks 192..255 : wc_rcr row  = W2rcr[row] @ Wd_top
//   block 256       : bc_r = b2cr @ Wd_bot
//   block 257       : bc_c = b2rc @ Wd_top
__global__ void fold_k(const float* __restrict__ W2crl, const float* __restrict__ W2crr,
                       const float* __restrict__ W2rcl, const float* __restrict__ W2rcr,
                       const float* __restrict__ b2cr,  const float* __restrict__ b2rc,
                       const float* __restrict__ Wd_top, const float* __restrict__ Wd_bot,
                       float* __restrict__ wc_crl, float* __restrict__ wc_crr,
                       float* __restrict__ wc_rcl, float* __restrict__ wc_rcr,
                       float* __restrict__ bc_r, float* __restrict__ bc_c) {
    __shared__ float Ar[HD];
    int b = blockIdx.x, j = threadIdx.x;
    const float *Arow, *B;
    float* Crow;
    if (b < 256) {
        int which = b >> 6, r = b & 63;
        switch (which) {
            case 0: Arow = W2crl + r * HD; B = Wd_bot; Crow = wc_crl + r * HD; break;
            case 1: Arow = W2crr + r * HD; B = Wd_bot; Crow = wc_crr + r * HD; break;
            case 2: Arow = W2rcl + r * HD; B = Wd_top; Crow = wc_rcl + r * HD; break;
            default:Arow = W2rcr + r * HD; B = Wd_top; Crow = wc_rcr + r * HD; break;
        }
    } else if (b == 256) { Arow = b2cr; B = Wd_bot; Crow = bc_r; }
    else                 { Arow = b2rc; B = Wd_top; Crow = bc_c; }
    Ar[j] = Arow[j];
    __syncthreads();
    float s = 0.f;
#pragma unroll 16
    for (int k = 0; k < HD; k++) s += Ar[k] * B[k * HD + j];
    Crow[j] = s;
}

// Y[n,64] = X[n,K] @ W[K,64].  W cached in shared; one thread per row.
__global__ void gemm_nk(const float* __restrict__ X, const float* __restrict__ W,
                        float* __restrict__ Y, int n, int K) {
    extern __shared__ float Ws[]; // K*64
    for (int i = threadIdx.x; i < K * HD; i += blockDim.x) Ws[i] = W[i];
    __syncthreads();
    int row = blockIdx.x * blockDim.x + threadIdx.x;
    if (row >= n) return;
    float acc[HD];
#pragma unroll
    for (int j = 0; j < HD; j++) acc[j] = 0.f;
    const float* xr = X + (size_t)row * K;
    for (int k = 0; k < K; k += 4) {
        float4 xv = *reinterpret_cast<const float4*>(xr + k);
        float xs[4] = {xv.x, xv.y, xv.z, xv.w};
#pragma unroll
        for (int kk = 0; kk < 4; kk++) {
            const float4* wrow = reinterpret_cast<const float4*>(Ws + (k + kk) * HD);
            float x = xs[kk];
#pragma unroll
            for (int j4 = 0; j4 < HD / 4; j4++) {
                float4 w = wrow[j4];
                acc[j4 * 4 + 0] += x * w.x;
                acc[j4 * 4 + 1] += x * w.y;
                acc[j4 * 4 + 2] += x * w.z;
                acc[j4 * 4 + 3] += x * w.w;
            }
        }
    }
    float4* yr = reinterpret_cast<float4*>(Y + (size_t)row * HD);
#pragma unroll
    for (int j4 = 0; j4 < HD / 4; j4++)
        yr[j4] = make_float4(acc[j4 * 4], acc[j4 * 4 + 1], acc[j4 * 4 + 2], acc[j4 * 4 + 3]);
}

// Fused gather-aggregate + mean + self + bias (+relu).
// One warp per dst node; float2 per lane (64 floats / row).  [R2-proven version]
__global__ void aggregate_k(const float* __restrict__ feat, const float* __restrict__ self,
                            const float* __restrict__ bias, const int* __restrict__ offs,
                            const int* __restrict__ deg, const int* __restrict__ csr,
                            float* __restrict__ out, int n, int do_relu) {
    int w    = (blockIdx.x * blockDim.x + threadIdx.x) >> 5;
    int lane = threadIdx.x & 31;
    if (w >= n) return;
    int beg = __ldg(offs + w);
    int dg  = __ldg(deg + w);
    int end = beg + dg;
    float ax = 0.f, ay = 0.f, bx = 0.f, by = 0.f;
    int e = beg;
    for (; e + 1 < end; e += 2) {
        int s0 = __ldg(csr + e);
        int s1 = __ldg(csr + e + 1);
        float2 v0 = reinterpret_cast<const float2*>(feat + (size_t)s0 * HD)[lane];
        float2 v1 = reinterpret_cast<const float2*>(feat + (size_t)s1 * HD)[lane];
        ax += v0.x; ay += v0.y;
        bx += v1.x; by += v1.y;
    }
    if (e < end) {
        int s0 = __ldg(csr + e);
        float2 v0 = reinterpret_cast<const float2*>(feat + (size_t)s0 * HD)[lane];
        ax += v0.x; ay += v0.y;
    }
    ax += bx; ay += by;
    float inv = 1.f / (float)max(dg, 1);
    float2 sf = reinterpret_cast<const float2*>(self + (size_t)w * HD)[lane];
    float2 bb = reinterpret_cast<const float2*>(bias)[lane];
    float o0 = ax * inv + sf.x + bb.x;
    float o1 = ay * inv + sf.y + bb.y;
    if (do_relu) { o0 = fmaxf(o0, 0.f); o1 = fmaxf(o1, 0.f); }
    reinterpret_cast<float2*>(out + (size_t)w * HD)[lane] = make_float2(o0, o1);
}

// warp per supervision edge: out = relu(u_c[r]+u_r[c]+b1) . w2 + b2
__global__ void decode_k(const float* __restrict__ u_c, const float* __restrict__ u_r,
                         const int* __restrict__ rows, const int* __restrict__ cols,
                         const float* __restrict__ b1, const float* __restrict__ w2,
                         const float* __restrict__ b2, float* __restrict__ out, int L) {
    int gw   = (blockIdx.x * blockDim.x + threadIdx.x) >> 5;
    int lane = threadIdx.x & 31;
    if (gw >= L) return;
    int r = __ldg(rows + gw);
    int c = __ldg(cols + gw);
    float2 a  = reinterpret_cast<const float2*>(u_c + (size_t)r * HD)[lane];
    float2 b  = reinterpret_cast<const float2*>(u_r + (size_t)c * HD)[lane];
    float2 bb = reinterpret_cast<const float2*>(b1)[lane];
    float2 w  = reinterpret_cast<const float2*>(w2)[lane];
    float h0 = fmaxf(a.x + b.x + bb.x, 0.f);
    float h1 = fmaxf(a.y + b.y + bb.y, 0.f);
    float s = h0 * w.x + h1 * w.y;
#pragma unroll
    for (int off = 16; off; off >>= 1) s += __shfl_xor_sync(0xffffffffu, s, off);
    if (lane == 0) out[gw] = s + __ldg(b2);
}

// ---------------- launch ----------------

extern "C" void kernel_launch(void* const* d_in, const int* in_sizes, int n_in,
                              void* d_out, int out_size) {
    const float* x_c   = (const float*)d_in[0];
    const float* x_r   = (const float*)d_in[1];
    const float* W1crl = (const float*)d_in[2];
    const float* W1crr = (const float*)d_in[3];
    const float* b1cr  = (const float*)d_in[4];
    const float* W1rcl = (const float*)d_in[5];
    const float* W1rcr = (const float*)d_in[6];
    const float* b1rc  = (const float*)d_in[7];
    const float* W2crl = (const float*)d_in[8];
    const float* W2crr = (const float*)d_in[9];
    const float* b2cr  = (const float*)d_in[10];
    const float* W2rcl = (const float*)d_in[11];
    const float* W2rcr = (const float*)d_in[12];
    const float* b2rc  = (const float*)d_in[13];
    const float* Wd1   = (const float*)d_in[14];  // [128,64]
    const float* bd1   = (const float*)d_in[15];
    const float* Wd2   = (const float*)d_in[16];
    const float* bd2   = (const float*)d_in[17];
    const int*   e_cr  = (const int*)d_in[18];
    const int*   e_rc  = (const int*)d_in[19];
    const int*   e_lab = (const int*)d_in[20];
    const int E_ = in_sizes[18] / 2;
    const int L_ = in_sizes[20] / 2;

    float *t_c, *t_r, *s_r, *s_c, *h_r, *h_c;
    float *wc_crl, *wc_crr, *wc_rcl, *wc_rcr, *bc_r, *bc_c;
    int *dg_r, *dg_c, *off_r, *off_c, *cur_r, *cur_c, *csr_cr, *csr_rc, *bsum;
    cudaGetSymbolAddress((void**)&t_c, g_t_c);
    cudaGetSymbolAddress((void**)&t_r, g_t_r);
    cudaGetSymbolAddress((void**)&s_r, g_s_r);
    cudaGetSymbolAddress((void**)&s_c, g_s_c);
    cudaGetSymbolAddress((void**)&h_r, g_h_r);
    cudaGetSymbolAddress((void**)&h_c, g_h_c);
    cudaGetSymbolAddress((void**)&dg_r, g_dg_r);
    cudaGetSymbolAddress((void**)&dg_c, g_dg_c);
    cudaGetSymbolAddress((void**)&off_r, g_off_r);
    cudaGetSymbolAddress((void**)&off_c, g_off_c);
    cudaGetSymbolAddress((void**)&cur_r, g_cur_r);
    cudaGetSymbolAddress((void**)&cur_c, g_cur_c);
    cudaGetSymbolAddress((void**)&csr_cr, g_csr_cr);
    cudaGetSymbolAddress((void**)&csr_rc, g_csr_rc);
    cudaGetSymbolAddress((void**)&bsum, g_bsum);
    cudaGetSymbolAddress((void**)&wc_crl, g_wc_crl);
    cudaGetSymbolAddress((void**)&wc_crr, g_wc_crr);
    cudaGetSymbolAddress((void**)&wc_rcl, g_wc_rcl);
    cudaGetSymbolAddress((void**)&wc_rcr, g_wc_rcr);
    cudaGetSymbolAddress((void**)&bc_r, g_bc_r);
    cudaGetSymbolAddress((void**)&bc_c, g_bc_c);

    const int NT = 256;
    const int gD4  = (NCN / 4 + NT - 1) / NT;
    const int gRow = (NCN + NT - 1) / NT;
    const int gE   = (E_ + NT - 1) / NT;
    const int gNw  = (NCN * 32 + NT - 1) / NT;
    const int gLw  = (L_ * 32 + NT - 1) / NT;
    const int nScanB = (NCN + SCAN_BS - 1) / SCAN_BS;

    const int* cr_s = e_cr;   const int* cr_d = e_cr + E_;
    const int* rc_s = e_rc;   const int* rc_d = e_rc + E_;
    const int* lb_r = e_lab;  const int* lb_c = e_lab + L_;

    const float* Wd_top = Wd1;            // rows 0..63  (z_c half)
    const float* Wd_bot = Wd1 + HD * HD;  // rows 64..127 (z_r half)

    // ---- decoder fold: one launch ----
    fold_k<<<258, HD>>>(W2crl, W2crr, W2rcl, W2rcr, b2cr, b2rc, Wd_top, Wd_bot,
                        wc_crl, wc_crr, wc_rcl, wc_rcr, bc_r, bc_c);

    // ---- degrees ----
    zero_i4<<<gD4, NT>>>((int4*)dg_r, NRN / 4);
    zero_i4<<<gD4, NT>>>((int4*)dg_c, NCN / 4);
    degree_k<<<gE, NT>>>(cr_d, dg_r, E_);
    degree_k<<<gE, NT>>>(rc_d, dg_c, E_);

    // ---- CSR build ----
    scan_block_k<<<nScanB, SCAN_BS>>>(dg_r, off_r, bsum, NRN);
    scan_sums_k<<<1, 1024>>>(bsum, nScanB);
    scan_add_copy_k<<<nScanB, SCAN_BS>>>(off_r, cur_r, bsum, NRN);
    csr_fill_k<<<gE, NT>>>(cr_s, cr_d, cur_r, csr_cr, E_);
    scan_block_k<<<nScanB, SCAN_BS>>>(dg_c, off_c, bsum, NCN);
    scan_sums_k<<<1, 1024>>>(bsum, nScanB);
    scan_add_copy_k<<<nScanB, SCAN_BS>>>(off_c, cur_c, bsum, NCN);
    csr_fill_k<<<gE, NT>>>(rc_s, rc_d, cur_c, csr_rc, E_);

    // ---- layer 1 transforms ----
    gemm_nk<<<gRow, NT, 128 * HD * sizeof(float)>>>(x_c, W1crl, t_c, NCN, 128);
    gemm_nk<<<gRow, NT,  64 * HD * sizeof(float)>>>(x_r, W1crr, s_r, NRN, 64);
    gemm_nk<<<gRow, NT,  64 * HD * sizeof(float)>>>(x_r, W1rcl, t_r, NRN, 64);
    gemm_nk<<<gRow, NT, 128 * HD * sizeof(float)>>>(x_c, W1rcr, s_c, NCN, 128);

    // ---- layer 1 aggregate (relu) ----
    aggregate_k<<<gNw, NT>>>(t_c, s_r, b1cr, off_r, dg_r, csr_cr, h_r, NRN, 1);
    aggregate_k<<<gNw, NT>>>(t_r, s_c, b1rc, off_c, dg_c, csr_rc, h_c, NCN, 1);

    // ---- layer 2 transforms, pre-multiplied into decoder space ----
    gemm_nk<<<gRow, NT, 64 * HD * sizeof(float)>>>(h_c, wc_crl, t_c, NCN, 64); // msg c->r
    gemm_nk<<<gRow, NT, 64 * HD * sizeof(float)>>>(h_r, wc_crr, s_r, NRN, 64); // self r
    gemm_nk<<<gRow, NT, 64 * HD * sizeof(float)>>>(h_r, wc_rcl, t_r, NRN, 64); // msg r->c
    gemm_nk<<<gRow, NT, 64 * HD * sizeof(float)>>>(h_c, wc_rcr, s_c, NCN, 64); // self c

    // ---- layer 2 aggregate -> directly u_r (in h_r) and u_c (in h_c) ----
    aggregate_k<<<gNw, NT>>>(t_c, s_r, bc_r, off_r, dg_r, csr_cr, h_r, NRN, 0);
    aggregate_k<<<gNw, NT>>>(t_r, s_c, bc_c, off_c, dg_c, csr_rc, h_c, NCN, 0);

    // ---- decode (u_c = h_c, u_r = h_r) ----
    decode_k<<<gLw, NT>>>(h_c, h_r, lb_r, lb_c, bd1, Wd2, bd2, (float*)d_out, L_);
}

// round 6
// speedup vs baseline: 1.3970x; 1.0655x over previous
#include <cuda_runtime.h>
#include <cuda_bf16.h>
#include <stdint.h>

#define NCN 100000
#define NRN 100000
#define HD  64
#define EMAX 2000000
#define SCAN_BS 256
#define NSCANB 391   // ceil(100000/256)

// ---------------- scratch (device globals: allocation-free) ----------------
__device__ float g_t_c[(size_t)NCN * HD];
__device__ float g_t_r[(size_t)NRN * HD];
__device__ float g_s_r[(size_t)NRN * HD];
__device__ float g_s_c[(size_t)NCN * HD];
__device__ float g_h_r[(size_t)NRN * HD];
__device__ float g_h_c[(size_t)NCN * HD];
__device__ int   g_dg_r[NRN];
__device__ int   g_dg_c[NCN];
__device__ int   g_off_r[NRN];
__device__ int   g_off_c[NCN];
__device__ int   g_cur_r[NRN];
__device__ int   g_cur_c[NCN];
__device__ int   g_csr_cr[EMAX];
__device__ int   g_csr_rc[EMAX];
__device__ int   g_bsum[2 * NSCANB + 2];
// folded decoder weights/biases
__device__ float g_wc_crl[HD * HD];  // W2crl @ Wd_bot   (msg c->r, feeds u_r)
__device__ float g_wc_crr[HD * HD];  // W2crr @ Wd_bot   (self r,  feeds u_r)
__device__ float g_wc_rcl[HD * HD];  // W2rcl @ Wd_top   (msg r->c, feeds u_c)
__device__ float g_wc_rcr[HD * HD];  // W2rcr @ Wd_top   (self c,  feeds u_c)
__device__ float g_bc_r[HD];         // b2cr @ Wd_bot
__device__ float g_bc_c[HD];         // b2rc @ Wd_top

// ---------------- kernels ----------------

// zero both degree arrays in one launch
__global__ void zero2_k(int4* __restrict__ a, int4* __restrict__ b, int n4) {
    int i = blockIdx.x * blockDim.x + threadIdx.x;
    if (i < n4) a[i] = make_int4(0, 0, 0, 0);
    else if (i < 2 * n4) b[i - n4] = make_int4(0, 0, 0, 0);
}

// both relations' degree counts in one launch
__global__ void degree2_k(const int* __restrict__ dstA, int* __restrict__ degA,
                          const int* __restrict__ dstB, int* __restrict__ degB, int nE) {
    int i = blockIdx.x * blockDim.x + threadIdx.x;
    if (i < nE) atomicAdd(degA + __ldg(dstA + i), 1);
    else if (i < 2 * nE) atomicAdd(degB + __ldg(dstB + (i - nE)), 1);
}

// --- segmented 3-kernel exclusive scan: segment 0 = relation A, 1 = relation B ---
__global__ void scan_block2_k(const int* __restrict__ inA, int* __restrict__ outA,
                              const int* __restrict__ inB, int* __restrict__ outB,
                              int* __restrict__ bsum, int n) {
    __shared__ int sh[SCAN_BS];
    int b = blockIdx.x;
    const int* in;
    int* out;
    int lb;
    if (b < NSCANB) { in = inA; out = outA; lb = b; }
    else            { in = inB; out = outB; lb = b - NSCANB; }
    int i = lb * SCAN_BS + threadIdx.x;
    int v = (i < n) ? in[i] : 0;
    sh[threadIdx.x] = v;
    __syncthreads();
    for (int off = 1; off < SCAN_BS; off <<= 1) {
        int t = (threadIdx.x >= off) ? sh[threadIdx.x - off] : 0;
        __syncthreads();
        sh[threadIdx.x] += t;
        __syncthreads();
    }
    if (i < n) out[i] = sh[threadIdx.x] - v;
    if (threadIdx.x == SCAN_BS - 1) bsum[b] = sh[threadIdx.x];
}

__global__ void scan_sums2_k(int* __restrict__ bsum) {  // 2 blocks, one per segment
    __shared__ int sh[1024];
    int* seg = bsum + blockIdx.x * NSCANB;
    int v = (threadIdx.x < NSCANB) ? seg[threadIdx.x] : 0;
    sh[threadIdx.x] = v;
    __syncthreads();
    for (int off = 1; off < 1024; off <<= 1) {
        int t = (threadIdx.x >= off) ? sh[threadIdx.x - off] : 0;
        __syncthreads();
        sh[threadIdx.x] += t;
        __syncthreads();
    }
    if (threadIdx.x < NSCANB) seg[threadIdx.x] = sh[threadIdx.x] - v;
}

__global__ void scan_add_copy2_k(int* __restrict__ outA, int* __restrict__ curA,
                                 int* __restrict__ outB, int* __restrict__ curB,
                                 const int* __restrict__ bsum, int n) {
    int b = blockIdx.x;
    int* out;
    int* cur;
    int lb;
    if (b < NSCANB) { out = outA; cur = curA; lb = b; }
    else            { out = outB; cur = curB; lb = b - NSCANB; }
    int i = lb * SCAN_BS + threadIdx.x;
    if (i < n) {
        int v = out[i] + bsum[b];
        out[i] = v;
        cur[i] = v;
    }
}

// both relations' CSR fill in one launch
__global__ void csr_fill2_k(const int* __restrict__ srcA, const int* __restrict__ dstA,
                            int* __restrict__ curA, int* __restrict__ csrA,
                            const int* __restrict__ srcB, const int* __restrict__ dstB,
                            int* __restrict__ curB, int* __restrict__ csrB, int nE) {
    int i = blockIdx.x * blockDim.x + threadIdx.x;
    if (i < nE) {
        int d = __ldg(dstA + i);
        int p = atomicAdd(curA + d, 1);
        csrA[p] = __ldg(srcA + i);
    } else if (i < 2 * nE) {
        int j = i - nE;
        int d = __ldg(dstB + j);
        int p = atomicAdd(curB + d, 1);
        csrB[p] = __ldg(srcB + j);
    }
}

// One launch for the whole decoder fold (258 blocks of 64 threads).
__global__ void fold_k(const float* __restrict__ W2crl, const float* __restrict__ W2crr,
                       const float* __restrict__ W2rcl, const float* __restrict__ W2rcr,
                       const float* __restrict__ b2cr,  const float* __restrict__ b2rc,
                       const float* __restrict__ Wd_top, const float* __restrict__ Wd_bot,
                       float* __restrict__ wc_crl, float* __restrict__ wc_crr,
                       float* __restrict__ wc_rcl, float* __restrict__ wc_rcr,
                       float* __restrict__ bc_r, float* __restrict__ bc_c) {
    __shared__ float Ar[HD];
    int b = blockIdx.x, j = threadIdx.x;
    const float *Arow, *B;
    float* Crow;
    if (b < 256) {
        int which = b >> 6, r = b & 63;
        switch (which) {
            case 0: Arow = W2crl + r * HD; B = Wd_bot; Crow = wc_crl + r * HD; break;
            case 1: Arow = W2crr + r * HD; B = Wd_bot; Crow = wc_crr + r * HD; break;
            case 2: Arow = W2rcl + r * HD; B = Wd_top; Crow = wc_rcl + r * HD; break;
            default:Arow = W2rcr + r * HD; B = Wd_top; Crow = wc_rcr + r * HD; break;
        }
    } else if (b == 256) { Arow = b2cr; B = Wd_bot; Crow = bc_r; }
    else                 { Arow = b2rc; B = Wd_top; Crow = bc_c; }
    Ar[j] = Arow[j];
    __syncthreads();
    float s = 0.f;
#pragma unroll 16
    for (int k = 0; k < HD; k++) s += Ar[k] * B[k * HD + j];
    Crow[j] = s;
}

// Y[n,64] = X[n,K] @ W[K,64].  W cached in shared; one thread per row.
__global__ void gemm_nk(const float* __restrict__ X, const float* __restrict__ W,
                        float* __restrict__ Y, int n, int K) {
    extern __shared__ float Ws[]; // K*64
    for (int i = threadIdx.x; i < K * HD; i += blockDim.x) Ws[i] = W[i];
    __syncthreads();
    int row = blockIdx.x * blockDim.x + threadIdx.x;
    if (row >= n) return;
    float acc[HD];
#pragma unroll
    for (int j = 0; j < HD; j++) acc[j] = 0.f;
    const float* xr = X + (size_t)row * K;
    for (int k = 0; k < K; k += 4) {
        float4 xv = *reinterpret_cast<const float4*>(xr + k);
        float xs[4] = {xv.x, xv.y, xv.z, xv.w};
#pragma unroll
        for (int kk = 0; kk < 4; kk++) {
            const float4* wrow = reinterpret_cast<const float4*>(Ws + (k + kk) * HD);
            float x = xs[kk];
#pragma unroll
            for (int j4 = 0; j4 < HD / 4; j4++) {
                float4 w = wrow[j4];
                acc[j4 * 4 + 0] += x * w.x;
                acc[j4 * 4 + 1] += x * w.y;
                acc[j4 * 4 + 2] += x * w.z;
                acc[j4 * 4 + 3] += x * w.w;
            }
        }
    }
    float4* yr = reinterpret_cast<float4*>(Y + (size_t)row * HD);
#pragma unroll
    for (int j4 = 0; j4 < HD / 4; j4++)
        yr[j4] = make_float4(acc[j4 * 4], acc[j4 * 4 + 1], acc[j4 * 4 + 2], acc[j4 * 4 + 3]);
}

// Fused gather-aggregate + mean + self + bias (+relu).
// 16 lanes per dst node (float4 per lane); two nodes per warp.
__global__ void aggregate16_k(const float* __restrict__ feat, const float* __restrict__ self,
                              const float* __restrict__ bias, const int* __restrict__ offs,
                              const int* __restrict__ deg, const int* __restrict__ csr,
                              float* __restrict__ out, int n, int do_relu) {
    int g = (blockIdx.x * blockDim.x + threadIdx.x) >> 4;  // node index
    int l = threadIdx.x & 15;
    if (g >= n) return;
    int beg = __ldg(offs + g);
    int dg  = __ldg(deg + g);
    int end = beg + dg;
    const float4* feat4 = reinterpret_cast<const float4*>(feat);
    float4 a0 = make_float4(0.f, 0.f, 0.f, 0.f);
    float4 a1 = make_float4(0.f, 0.f, 0.f, 0.f);
    int e = beg;
    for (; e + 1 < end; e += 2) {
        int s0 = __ldg(csr + e);
        int s1 = __ldg(csr + e + 1);
        float4 v0 = feat4[(size_t)s0 * 16 + l];
        float4 v1 = feat4[(size_t)s1 * 16 + l];
        a0.x += v0.x; a0.y += v0.y; a0.z += v0.z; a0.w += v0.w;
        a1.x += v1.x; a1.y += v1.y; a1.z += v1.z; a1.w += v1.w;
    }
    if (e < end) {
        int s0 = __ldg(csr + e);
        float4 v0 = feat4[(size_t)s0 * 16 + l];
        a0.x += v0.x; a0.y += v0.y; a0.z += v0.z; a0.w += v0.w;
    }
    float inv = 1.f / (float)max(dg, 1);
    float4 sf = reinterpret_cast<const float4*>(self)[(size_t)g * 16 + l];
    float4 bb = reinterpret_cast<const float4*>(bias)[l];
    float4 o;
    o.x = (a0.x + a1.x) * inv + sf.x + bb.x;
    o.y = (a0.y + a1.y) * inv + sf.y + bb.y;
    o.z = (a0.z + a1.z) * inv + sf.z + bb.z;
    o.w = (a0.w + a1.w) * inv + sf.w + bb.w;
    if (do_relu) {
        o.x = fmaxf(o.x, 0.f); o.y = fmaxf(o.y, 0.f);
        o.z = fmaxf(o.z, 0.f); o.w = fmaxf(o.w, 0.f);
    }
    reinterpret_cast<float4*>(out)[(size_t)g * 16 + l] = o;
}

// 16 lanes per supervision edge: out = relu(u_c[r]+u_r[c]+b1) . w2 + b2
__global__ void decode16_k(const float* __restrict__ u_c, const float* __restrict__ u_r,
                           const int* __restrict__ rows, const int* __restrict__ cols,
                           const float* __restrict__ b1, const float* __restrict__ w2,
                           const float* __restrict__ b2, float* __restrict__ out, int L) {
    int g = (blockIdx.x * blockDim.x + threadIdx.x) >> 4;
    int l = threadIdx.x & 15;
    if (g >= L) return;
    int r = __ldg(rows + g);
    int c = __ldg(cols + g);
    float4 a  = reinterpret_cast<const float4*>(u_c)[(size_t)r * 16 + l];
    float4 b  = reinterpret_cast<const float4*>(u_r)[(size_t)c * 16 + l];
    float4 bb = reinterpret_cast<const float4*>(b1)[l];
    float4 w  = reinterpret_cast<const float4*>(w2)[l];
    float h0 = fmaxf(a.x + b.x + bb.x, 0.f);
    float h1 = fmaxf(a.y + b.y + bb.y, 0.f);
    float h2 = fmaxf(a.z + b.z + bb.z, 0.f);
    float h3 = fmaxf(a.w + b.w + bb.w, 0.f);
    float s = (h0 * w.x + h1 * w.y) + (h2 * w.z + h3 * w.w);
#pragma unroll
    for (int off = 8; off; off >>= 1) s += __shfl_xor_sync(0xffffffffu, s, off);
    if (l == 0) out[g] = s + __ldg(b2);
}

// ---------------- launch ----------------

extern "C" void kernel_launch(void* const* d_in, const int* in_sizes, int n_in,
                              void* d_out, int out_size) {
    const float* x_c   = (const float*)d_in[0];
    const float* x_r   = (const float*)d_in[1];
    const float* W1crl = (const float*)d_in[2];
    const float* W1crr = (const float*)d_in[3];
    const float* b1cr  = (const float*)d_in[4];
    const float* W1rcl = (const float*)d_in[5];
    const float* W1rcr = (const float*)d_in[6];
    const float* b1rc  = (const float*)d_in[7];
    const float* W2crl = (const float*)d_in[8];
    const float* W2crr = (const float*)d_in[9];
    const float* b2cr  = (const float*)d_in[10];
    const float* W2rcl = (const float*)d_in[11];
    const float* W2rcr = (const float*)d_in[12];
    const float* b2rc  = (const float*)d_in[13];
    const float* Wd1   = (const float*)d_in[14];  // [128,64]
    const float* bd1   = (const float*)d_in[15];
    const float* Wd2   = (const float*)d_in[16];
    const float* bd2   = (const float*)d_in[17];
    const int*   e_cr  = (const int*)d_in[18];
    const int*   e_rc  = (const int*)d_in[19];
    const int*   e_lab = (const int*)d_in[20];
    const int E_ = in_sizes[18] / 2;
    const int L_ = in_sizes[20] / 2;

    float *t_c, *t_r, *s_r, *s_c, *h_r, *h_c;
    float *wc_crl, *wc_crr, *wc_rcl, *wc_rcr, *bc_r, *bc_c;
    int *dg_r, *dg_c, *off_r, *off_c, *cur_r, *cur_c, *csr_cr, *csr_rc, *bsum;
    cudaGetSymbolAddress((void**)&t_c, g_t_c);
    cudaGetSymbolAddress((void**)&t_r, g_t_r);
    cudaGetSymbolAddress((void**)&s_r, g_s_r);
    cudaGetSymbolAddress((void**)&s_c, g_s_c);
    cudaGetSymbolAddress((void**)&h_r, g_h_r);
    cudaGetSymbolAddress((void**)&h_c, g_h_c);
    cudaGetSymbolAddress((void**)&dg_r, g_dg_r);
    cudaGetSymbolAddress((void**)&dg_c, g_dg_c);
    cudaGetSymbolAddress((void**)&off_r, g_off_r);
    cudaGetSymbolAddress((void**)&off_c, g_off_c);
    cudaGetSymbolAddress((void**)&cur_r, g_cur_r);
    cudaGetSymbolAddress((void**)&cur_c, g_cur_c);
    cudaGetSymbolAddress((void**)&csr_cr, g_csr_cr);
    cudaGetSymbolAddress((void**)&csr_rc, g_csr_rc);
    cudaGetSymbolAddress((void**)&bsum, g_bsum);
    cudaGetSymbolAddress((void**)&wc_crl, g_wc_crl);
    cudaGetSymbolAddress((void**)&wc_crr, g_wc_crr);
    cudaGetSymbolAddress((void**)&wc_rcl, g_wc_rcl);
    cudaGetSymbolAddress((void**)&wc_rcr, g_wc_rcr);
    cudaGetSymbolAddress((void**)&bc_r, g_bc_r);
    cudaGetSymbolAddress((void**)&bc_c, g_bc_c);

    const int NT = 256;
    const int gRow  = (NCN + NT - 1) / NT;
    const int gE2   = (2 * E_ + NT - 1) / NT;
    const int gZ2   = (2 * (NCN / 4) + NT - 1) / NT;
    const int gN16  = (NCN * 16 + NT - 1) / NT;
    const int gL16  = (L_ * 16 + NT - 1) / NT;

    const int* cr_s = e_cr;   const int* cr_d = e_cr + E_;
    const int* rc_s = e_rc;   const int* rc_d = e_rc + E_;
    const int* lb_r = e_lab;  const int* lb_c = e_lab + L_;

    const float* Wd_top = Wd1;            // rows 0..63  (z_c half)
    const float* Wd_bot = Wd1 + HD * HD;  // rows 64..127 (z_r half)

    // ---- decoder fold: one launch ----
    fold_k<<<258, HD>>>(W2crl, W2crr, W2rcl, W2rcr, b2cr, b2rc, Wd_top, Wd_bot,
                        wc_crl, wc_crr, wc_rcl, wc_rcr, bc_r, bc_c);

    // ---- degrees (both relations) ----
    zero2_k<<<gZ2, NT>>>((int4*)dg_r, (int4*)dg_c, NRN / 4);
    degree2_k<<<gE2, NT>>>(cr_d, dg_r, rc_d, dg_c, E_);

    // ---- CSR build (both relations, segmented scan) ----
    scan_block2_k<<<2 * NSCANB, SCAN_BS>>>(dg_r, off_r, dg_c, off_c, bsum, NCN);
    scan_sums2_k<<<2, 1024>>>(bsum);
    scan_add_copy2_k<<<2 * NSCANB, SCAN_BS>>>(off_r, cur_r, off_c, cur_c, bsum, NCN);
    csr_fill2_k<<<gE2, NT>>>(cr_s, cr_d, cur_r, csr_cr, rc_s, rc_d, cur_c, csr_rc, E_);

    // ---- layer 1 transforms ----
    gemm_nk<<<gRow, NT, 128 * HD * sizeof(float)>>>(x_c, W1crl, t_c, NCN, 128);
    gemm_nk<<<gRow, NT,  64 * HD * sizeof(float)>>>(x_r, W1crr, s_r, NRN, 64);
    gemm_nk<<<gRow, NT,  64 * HD * sizeof(float)>>>(x_r, W1rcl, t_r, NRN, 64);
    gemm_nk<<<gRow, NT, 128 * HD * sizeof(float)>>>(x_c, W1rcr, s_c, NCN, 128);

    // ---- layer 1 aggregate (relu) ----
    aggregate16_k<<<gN16, NT>>>(t_c, s_r, b1cr, off_r, dg_r, csr_cr, h_r, NRN, 1);
    aggregate16_k<<<gN16, NT>>>(t_r, s_c, b1rc, off_c, dg_c, csr_rc, h_c, NCN, 1);

    // ---- layer 2 transforms, pre-multiplied into decoder space ----
    gemm_nk<<<gRow, NT, 64 * HD * sizeof(float)>>>(h_c, wc_crl, t_c, NCN, 64); // msg c->r
    gemm_nk<<<gRow, NT, 64 * HD * sizeof(float)>>>(h_r, wc_crr, s_r, NRN, 64); // self r
    gemm_nk<<<gRow, NT, 64 * HD * sizeof(float)>>>(h_r, wc_rcl, t_r, NRN, 64); // msg r->c
    gemm_nk<<<gRow, NT, 64 * HD * sizeof(float)>>>(h_c, wc_rcr, s_c, NCN, 64); // self c

    // ---- layer 2 aggregate -> directly u_r (in h_r) and u_c (in h_c) ----
    aggregate16_k<<<gN16, NT>>>(t_c, s_r, bc_r, off_r, dg_r, csr_cr, h_r, NRN, 0);
    aggregate16_k<<<gN16, NT>>>(t_r, s_c, bc_c, off_c, dg_c, csr_rc, h_c, NCN, 0);

    // ---- decode (u_c = h_c, u_r = h_r) ----
    decode16_k<<<gL16, NT>>>(h_c, h_r, lb_r, lb_c, bd1, Wd2, bd2, (float*)d_out, L_);
}